// round 11
// baseline (speedup 1.0000x reference)
#include <cuda_runtime.h>
#include <cstdint>

// ConcatenateMeanMax, two-pass feature-split version.
//
// out[b] = concat(bond_ft[b], mean(atom[s0],atom[s1]), max(atom[s0],atom[s1]))
// DEG = 2 fixed (edge_dst is repeat(arange(n_bonds), 2)).
//
// Pass h in {0,1} handles feature columns [64h, 64h+64) of bond copy, mean,
// and max. Rationale: the atom gather working set per pass is 51.2 MB (40% of
// the 126 MB L2) instead of 102.4 MB (81%), so the ~4x-reused table stays
// resident under store churn. Measured baseline (single-pass optimum): 1.030GB
// DRAM @ 6.56 TB/s = 156.8us ncu, with atom gathers at only ~50% L2 hit rate.
//
// Layout per pass: one warp per bond; each lane owns one float2 (8B);
// 32 lanes x 8B = 256B = the half-row. All loads/stores warp-contiguous.
// Hints per the measured R1-R8 matrix: __ldcs bond, __ldg atoms, __stcs out.

constexpr int D   = 128;
constexpr int DV2 = D / 2;      // 64 float2 per full row
constexpr int OV2 = 3 * DV2;    // 192 float2 per output row

__global__ __launch_bounds__(256)
void concat_mean_max_half_kernel(const float2* __restrict__ atom_ft,
                                 const float2* __restrict__ bond_ft,
                                 const int2*  __restrict__ edge_src2,
                                 float2* __restrict__ out,
                                 int n_bonds,
                                 int half)     // 0 or 1: column block [32h, 32h+32) in float2
{
    const int gwarp = (blockIdx.x * blockDim.x + threadIdx.x) >> 5;
    const int lane  = threadIdx.x & 31;
    if (gwarp >= n_bonds) return;

    const int col = half * 32 + lane;   // float2 column within the 64-float2 row

    const int2 s = __ldg(&edge_src2[gwarp]);

    // gathers first: the L2-resident table accesses (default caching)
    const float2 a0 = __ldg(&atom_ft[(long long)s.x * DV2 + col]);
    const float2 a1 = __ldg(&atom_ft[(long long)s.y * DV2 + col]);

    // read-once bond half-row: evict-first
    const float2 bf = __ldcs(&bond_ft[(long long)gwarp * DV2 + col]);

    float2 mean_v, max_v;
    mean_v.x = (a0.x + a1.x) * 0.5f;  max_v.x = fmaxf(a0.x, a1.x);
    mean_v.y = (a0.y + a1.y) * 0.5f;  max_v.y = fmaxf(a0.y, a1.y);

    float2* orow = out + (long long)gwarp * OV2;
    // write-once output: streaming stores, 256B contiguous per warp per region
    __stcs(orow + col,            bf);
    __stcs(orow + DV2 + col,      mean_v);
    __stcs(orow + 2 * DV2 + col,  max_v);
}

extern "C" void kernel_launch(void* const* d_in, const int* in_sizes, int n_in,
                              void* d_out, int out_size)
{
    const float2* atom_ft  = (const float2*)d_in[0];   // [N_ATOMS, 128] f32
    const float2* bond_ft  = (const float2*)d_in[1];   // [N_BONDS, 128] f32
    const int2*   edge_src = (const int2*)d_in[2];     // [N_BONDS*2] i32 -> int2 per bond
    // d_in[3] = edge_dst (structurally repeat(arange, 2)) -- not needed.

    const int n_bonds = in_sizes[1] / D;

    const int threads = 256;                 // 8 warps/block -> 8 bonds/block
    const int wpb = threads / 32;
    const int blocks = (n_bonds + wpb - 1) / wpb;

    // Two passes on the same stream (serialized by stream order, graph-safe).
    concat_mean_max_half_kernel<<<blocks, threads>>>(
        atom_ft, bond_ft, edge_src, (float2*)d_out, n_bonds, 0);
    concat_mean_max_half_kernel<<<blocks, threads>>>(
        atom_ft, bond_ft, edge_src, (float2*)d_out, n_bonds, 1);
}

// round 12
// speedup vs baseline: 1.0896x; 1.0896x over previous
#include <cuda_runtime.h>
#include <cstdint>

// ConcatenateMeanMax, two-pass feature-split, MLP-boosted.
//
// out[b] = concat(bond_ft[b], mean(atom[s0],atom[s1]), max(atom[s0],atom[s1]))
// DEG = 2 fixed (edge_dst is repeat(arange(n_bonds), 2)).
//
// Pass h in {0,1} handles feature columns [64h, 64h+64). Measured in R11: the
// per-pass 51.2MB atom working set stays L2-resident (total DRAM traffic fell
// 1.03GB -> 0.88GB), but 8B/lane accesses starved the memory system (5.08TB/s,
// DRAM 64%). This version restores throughput: float4 per lane, half-warp
// (16 lanes x 16B = 256B) per bond half-row, FOUR bonds per warp with all 12
// data loads issued before any compute/store (~3KB outstanding per warp).
// Hints per measured matrix: __ldcs bond, __ldg atoms, __stcs out.

constexpr int D    = 128;
constexpr int DV   = D / 4;     // 32 float4 per full row
constexpr int HV   = DV / 2;    // 16 float4 per half row
constexpr int OV   = 3 * DV;    // 96 float4 per output row

__global__ __launch_bounds__(256)
void concat_mean_max_half_kernel(const float4* __restrict__ atom_ft,
                                 const float4* __restrict__ bond_ft,
                                 const int4*  __restrict__ edge_src4,  // 2 bonds per int4
                                 float4* __restrict__ out,
                                 int n_bonds,
                                 int half)     // 0 or 1
{
    const int gwarp = (blockIdx.x * blockDim.x + threadIdx.x) >> 5;
    const int lane  = threadIdx.x & 31;

    const int base = gwarp * 4;            // 4 bonds per warp
    if (base >= n_bonds) return;

    const int p = lane >> 4;               // bond parity within pair (0/1)
    const int j = lane & 15;               // float4 column within half-row
    const int col = half * HV + j;         // float4 column within full row

    // indices for 4 bonds: two int4 broadcast loads
    const int4 s01 = __ldg(&edge_src4[gwarp * 2]);       // bonds base+0, base+1
    const int4 s23 = __ldg(&edge_src4[gwarp * 2 + 1]);   // bonds base+2, base+3

    const int b_a = base + p;        // iter 0 bond for this half-warp
    const int b_b = base + 2 + p;    // iter 1 bond
    const int sa0 = p ? s01.z : s01.x;
    const int sa1 = p ? s01.w : s01.y;
    const int sb0 = p ? s23.z : s23.x;
    const int sb1 = p ? s23.w : s23.y;

    const bool has_a = (b_a < n_bonds);
    const bool has_b = (b_b < n_bonds);

    // ---- issue all loads up front (up to 12 x 256B per warp in flight) ----
    float4 aa0, aa1, bfa, ba0, ba1, bfb;
    if (has_a) {
        aa0 = __ldg (&atom_ft[(long long)sa0 * DV + col]);
        aa1 = __ldg (&atom_ft[(long long)sa1 * DV + col]);
        bfa = __ldcs(&bond_ft[(long long)b_a * DV + col]);
    }
    if (has_b) {
        ba0 = __ldg (&atom_ft[(long long)sb0 * DV + col]);
        ba1 = __ldg (&atom_ft[(long long)sb1 * DV + col]);
        bfb = __ldcs(&bond_ft[(long long)b_b * DV + col]);
    }

    if (has_a) {
        float4 mean_v, max_v;
        mean_v.x = (aa0.x + aa1.x) * 0.5f;  max_v.x = fmaxf(aa0.x, aa1.x);
        mean_v.y = (aa0.y + aa1.y) * 0.5f;  max_v.y = fmaxf(aa0.y, aa1.y);
        mean_v.z = (aa0.z + aa1.z) * 0.5f;  max_v.z = fmaxf(aa0.z, aa1.z);
        mean_v.w = (aa0.w + aa1.w) * 0.5f;  max_v.w = fmaxf(aa0.w, aa1.w);
        float4* orow = out + (long long)b_a * OV;
        __stcs(orow + col,            bfa);
        __stcs(orow + DV + col,       mean_v);
        __stcs(orow + 2 * DV + col,   max_v);
    }
    if (has_b) {
        float4 mean_v, max_v;
        mean_v.x = (ba0.x + ba1.x) * 0.5f;  max_v.x = fmaxf(ba0.x, ba1.x);
        mean_v.y = (ba0.y + ba1.y) * 0.5f;  max_v.y = fmaxf(ba0.y, ba1.y);
        mean_v.z = (ba0.z + ba1.z) * 0.5f;  max_v.z = fmaxf(ba0.z, ba1.z);
        mean_v.w = (ba0.w + ba1.w) * 0.5f;  max_v.w = fmaxf(ba0.w, ba1.w);
        float4* orow = out + (long long)b_b * OV;
        __stcs(orow + col,            bfb);
        __stcs(orow + DV + col,       mean_v);
        __stcs(orow + 2 * DV + col,   max_v);
    }
}

extern "C" void kernel_launch(void* const* d_in, const int* in_sizes, int n_in,
                              void* d_out, int out_size)
{
    const float4* atom_ft  = (const float4*)d_in[0];   // [N_ATOMS, 128] f32
    const float4* bond_ft  = (const float4*)d_in[1];   // [N_BONDS, 128] f32
    const int4*   edge_src = (const int4*)d_in[2];     // [N_BONDS*2] i32
    // d_in[3] = edge_dst (structurally repeat(arange, 2)) -- not needed.

    const int n_bonds = in_sizes[1] / D;

    const int threads = 256;                      // 8 warps -> 32 bonds/block
    const int bonds_per_block = (threads / 32) * 4;
    const int blocks = (n_bonds + bonds_per_block - 1) / bonds_per_block;

    // Two passes, same stream (temporal separation keeps per-pass atom
    // working set = 51.2MB resident in L2).
    concat_mean_max_half_kernel<<<blocks, threads>>>(
        atom_ft, bond_ft, edge_src, (float4*)d_out, n_bonds, 0);
    concat_mean_max_half_kernel<<<blocks, threads>>>(
        atom_ft, bond_ft, edge_src, (float4*)d_out, n_bonds, 1);
}

// round 13
// speedup vs baseline: 1.1097x; 1.0185x over previous
#include <cuda_runtime.h>
#include <cstdint>

// ConcatenateMeanMax: out[b] = concat(bond_ft[b], mean(atom_ft[s0], atom_ft[s1]),
//                                     max(atom_ft[s0], atom_ft[s1]))
// DEG = 2 fixed (edge_dst is repeat(arange(n_bonds), 2)).
//
// FINAL (converged) config — global optimum of 12 measured variants:
//   - single fused kernel: 1536B output row written contiguously per warp
//     (split kernels lose 1.3-1.5 TB/s to 256B store granularity + 2x L1tex
//     wavefronts from half-warp addressing; measured R9/R11/R12)
//   - one warp per bond, float4 per lane: 512B fully-coalesced per row
//   - __ldcs bond (read-once) + __ldg atoms (reused) + __stcs out (write-once):
//     traffic minimum of the full hint matrix (1.030 GB vs 1.091 plain)
//   - deeper MLP / v8 width / ldcv / stwt / evict_last: all measured neutral
//     or worse; persisting-L2 carveout (the only true atom-table pin) is
//     forbidden by the harness device-limit guard.
// Practical roofline: 1.03 GB @ ~6.6 TB/s mixed-stream ceiling = ~156us ncu.

constexpr int D  = 128;
constexpr int DV = D / 4;  // 32 float4 per row

__global__ __launch_bounds__(256)
void concat_mean_max_kernel(const float4* __restrict__ atom_ft,
                            const float4* __restrict__ bond_ft,
                            const int2*  __restrict__ edge_src2,
                            float4* __restrict__ out,
                            int n_bonds)
{
    const int gwarp = (blockIdx.x * blockDim.x + threadIdx.x) >> 5;
    const int lane  = threadIdx.x & 31;
    if (gwarp >= n_bonds) return;

    const int2 s = __ldg(&edge_src2[gwarp]);

    // read-once bond row: evict-first load
    const float4 bf = __ldcs(&bond_ft[(long long)gwarp * DV + lane]);

    // reused atom rows: default caching (table competes for L2 residency)
    const float4 a0 = __ldg(&atom_ft[(long long)s.x * DV + lane]);
    const float4 a1 = __ldg(&atom_ft[(long long)s.y * DV + lane]);

    float4 mean_v, max_v;
    mean_v.x = (a0.x + a1.x) * 0.5f;  max_v.x = fmaxf(a0.x, a1.x);
    mean_v.y = (a0.y + a1.y) * 0.5f;  max_v.y = fmaxf(a0.y, a1.y);
    mean_v.z = (a0.z + a1.z) * 0.5f;  max_v.z = fmaxf(a0.z, a1.z);
    mean_v.w = (a0.w + a1.w) * 0.5f;  max_v.w = fmaxf(a0.w, a1.w);

    float4* orow = out + (long long)gwarp * (3 * DV);
    // write-once output: streaming stores, contiguous 1536B per bond row
    __stcs(orow + lane,          bf);
    __stcs(orow + DV + lane,     mean_v);
    __stcs(orow + 2 * DV + lane, max_v);
}

extern "C" void kernel_launch(void* const* d_in, const int* in_sizes, int n_in,
                              void* d_out, int out_size)
{
    const float4* atom_ft  = (const float4*)d_in[0];   // [N_ATOMS, 128] f32
    const float4* bond_ft  = (const float4*)d_in[1];   // [N_BONDS, 128] f32
    const int2*   edge_src = (const int2*)d_in[2];     // [N_BONDS*2] i32 -> int2 per bond
    // d_in[3] = edge_dst (structurally repeat(arange, 2)) -- not needed.

    const int n_bonds = in_sizes[1] / D;

    const int threads = 256;                 // 8 warps/block
    const int warps_per_block = threads / 32;
    const int blocks = (n_bonds + warps_per_block - 1) / warps_per_block;

    concat_mean_max_kernel<<<blocks, threads>>>(
        atom_ft, bond_ft, edge_src, (float4*)d_out, n_bonds);
}

// round 14
// speedup vs baseline: 1.1166x; 1.0062x over previous
#include <cuda_runtime.h>
#include <cstdint>

// ConcatenateMeanMax: out[b] = concat(bond_ft[b], mean(atom_ft[s0], atom_ft[s1]),
//                                     max(atom_ft[s0], atom_ft[s1]))
// DEG = 2 fixed (edge_dst is repeat(arange(n_bonds), 2)).
//
// R2-optimum layout (warp/bond, float4/lane, 1536B contiguous output rows,
// __ldcs bond + __stcs out) PLUS the one untried L2 mechanism: a dynamic
// createpolicy.fractional.L2::evict_last descriptor attached to the atom
// gathers via ld.global.nc.L2::cache_hint. Unlike the static .L2::evict_last
// qualifier (v8-only, measured no-op), this is the descriptor path that
// cudaAccessPolicyWindow lowers to, and it needs no device-limit change.
// Target: lift the atom table's ~50% L2 reuse hit rate -> traffic 1.03->0.95GB.

constexpr int D  = 128;
constexpr int DV = D / 4;  // 32 float4 per row

__device__ __forceinline__ float4 ldg_policy_v4(const float4* p, uint64_t pol) {
    float4 v;
    asm volatile("ld.global.nc.L2::cache_hint.v4.f32 {%0,%1,%2,%3}, [%4], %5;"
                 : "=f"(v.x), "=f"(v.y), "=f"(v.z), "=f"(v.w)
                 : "l"(p), "l"(pol));
    return v;
}

__global__ __launch_bounds__(256)
void concat_mean_max_kernel(const float4* __restrict__ atom_ft,
                            const float4* __restrict__ bond_ft,
                            const int2*  __restrict__ edge_src2,
                            float4* __restrict__ out,
                            int n_bonds)
{
    const int gwarp = (blockIdx.x * blockDim.x + threadIdx.x) >> 5;
    const int lane  = threadIdx.x & 31;
    if (gwarp >= n_bonds) return;

    // evict_last replacement-priority descriptor for the reused atom table
    uint64_t pol;
    asm("createpolicy.fractional.L2::evict_last.b64 %0, 1.0;" : "=l"(pol));

    const int2 s = __ldg(&edge_src2[gwarp]);

    // read-once bond row: evict-first load
    const float4 bf = __ldcs(&bond_ft[(long long)gwarp * DV + lane]);

    // reused atom rows: evict_last policy via cache_hint descriptor
    const float4 a0 = ldg_policy_v4(&atom_ft[(long long)s.x * DV + lane], pol);
    const float4 a1 = ldg_policy_v4(&atom_ft[(long long)s.y * DV + lane], pol);

    float4 mean_v, max_v;
    mean_v.x = (a0.x + a1.x) * 0.5f;  max_v.x = fmaxf(a0.x, a1.x);
    mean_v.y = (a0.y + a1.y) * 0.5f;  max_v.y = fmaxf(a0.y, a1.y);
    mean_v.z = (a0.z + a1.z) * 0.5f;  max_v.z = fmaxf(a0.z, a1.z);
    mean_v.w = (a0.w + a1.w) * 0.5f;  max_v.w = fmaxf(a0.w, a1.w);

    float4* orow = out + (long long)gwarp * (3 * DV);
    // write-once output: streaming stores, contiguous 1536B per bond row
    __stcs(orow + lane,          bf);
    __stcs(orow + DV + lane,     mean_v);
    __stcs(orow + 2 * DV + lane, max_v);
}

extern "C" void kernel_launch(void* const* d_in, const int* in_sizes, int n_in,
                              void* d_out, int out_size)
{
    const float4* atom_ft  = (const float4*)d_in[0];   // [N_ATOMS, 128] f32
    const float4* bond_ft  = (const float4*)d_in[1];   // [N_BONDS, 128] f32
    const int2*   edge_src = (const int2*)d_in[2];     // [N_BONDS*2] i32 -> int2 per bond
    // d_in[3] = edge_dst (structurally repeat(arange, 2)) -- not needed.

    const int n_bonds = in_sizes[1] / D;

    const int threads = 256;                 // 8 warps/block
    const int warps_per_block = threads / 32;
    const int blocks = (n_bonds + warps_per_block - 1) / warps_per_block;

    concat_mean_max_kernel<<<blocks, threads>>>(
        atom_ft, bond_ft, edge_src, (float4*)d_out, n_bonds);
}